// round 5
// baseline (speedup 1.0000x reference)
#include <cuda_runtime.h>

#define MAXN 100000
#define MAXE 3200000

// ---- device scratch (no allocations allowed) ----
__device__ float g_dinv[MAXN];
__device__ int   g_cnt [MAXN + 1];          // histogram (cnt[n] stays 0)
__device__ int   g_off [MAXN + 1];          // exclusive offsets (off[n] = E)
__device__ int   g_pos [MAXN];              // scatter cursors
__device__ int2  g_csr [MAXE];              // (row, w-bits) sorted by col
__device__ __align__(128) float4 g_xp  [MAXN];      // xs = dinv*x (w=0)
__device__ __align__(128) float4 g_aggx[MAXN];      // layer-0 pull result
__device__ __align__(128) float4 g_h4  [MAXN * 8];  // hs1 = dinv*relu(.) [N x 32]
__device__ __align__(128) float4 g_agg4[MAXN * 8];  // layer-1 pull result [N x 32]

// K1: zero histogram (n+1 entries)
__global__ void k_zero(int n) {
    int i = blockIdx.x * blockDim.x + threadIdx.x;
    if (i <= n) g_cnt[i] = 0;
}

// K2: histogram of target nodes
__global__ void k_hist(const int* __restrict__ idx, int E) {
    int e = blockIdx.x * blockDim.x + threadIdx.x;
    if (e >= E) return;
    atomicAdd(&g_cnt[idx[E + e]], 1);
}

// K3: single-block exclusive scan of n+1 counts -> g_off, g_pos
__global__ void k_scan(int n) {
    __shared__ int sdata[1024];
    int t = threadIdx.x;
    int total = n + 1;
    int chunk = (total + 1023) >> 10;
    int begin = t * chunk;
    int finish = min(begin + chunk, total);
    int sum = 0;
    for (int i = begin; i < finish; i++) sum += g_cnt[i];
    sdata[t] = sum;
    __syncthreads();
    for (int off = 1; off < 1024; off <<= 1) {
        int v = (t >= off) ? sdata[t - off] : 0;
        __syncthreads();
        sdata[t] += v;
        __syncthreads();
    }
    int run = sdata[t] - sum;  // exclusive prefix of this chunk
    for (int i = begin; i < finish; i++) {
        int c = g_cnt[i];
        g_off[i] = run;
        if (i < n) g_pos[i] = run;
        run += c;
    }
}

// K4: scatter edges into CSR slots (order within a node irrelevant)
__global__ void k_scatter(const int* __restrict__ idx, const float* __restrict__ w, int E) {
    int e = blockIdx.x * blockDim.x + threadIdx.x;
    if (e >= E) return;
    int row = idx[e];
    int col = idx[E + e];
    int p = atomicAdd(&g_pos[col], 1);
    g_csr[p] = make_int2(row, __float_as_int(w[e]));
}

// K5: warp/node: deg = 1 + sum(w) over CSR row (coalesced); dinv; xs = dinv*x
__global__ void k_degdinv(const float* __restrict__ x, int n) {
    int wid  = (blockIdx.x * blockDim.x + threadIdx.x) >> 5;
    int lane = threadIdx.x & 31;
    if (wid >= n) return;
    int s = g_off[wid], epos = g_off[wid + 1];
    float sum = 0.f;
    for (int e = s + lane; e < epos; e += 32) sum += __int_as_float(g_csr[e].y);
#pragma unroll
    for (int o = 16; o; o >>= 1) sum += __shfl_xor_sync(0xffffffffu, sum, o);
    float dv = rsqrtf(1.0f + sum);
    if (lane == 0) {
        g_dinv[wid] = dv;
        g_xp[wid] = make_float4(x[3*wid] * dv, x[3*wid+1] * dv, x[3*wid+2] * dv, 0.f);
    }
}

// K6: layer-0 pull: agg0[i] = xs[i] + sum_e w_e * xs[row_e]  (no atomics)
__global__ void k_pull0(int n) {
    int wid  = (blockIdx.x * blockDim.x + threadIdx.x) >> 5;
    int lane = threadIdx.x & 31;
    if (wid >= n) return;
    int s = g_off[wid], epos = g_off[wid + 1];
    float a0, a1, a2;
    if (lane == 0) { float4 xs = g_xp[wid]; a0 = xs.x; a1 = xs.y; a2 = xs.z; }
    else           { a0 = a1 = a2 = 0.f; }
    for (int e = s + lane; e < epos; e += 32) {
        int2 c = g_csr[e];
        float ww = __int_as_float(c.y);
        float4 v = g_xp[c.x];
        a0 = fmaf(ww, v.x, a0); a1 = fmaf(ww, v.y, a1); a2 = fmaf(ww, v.z, a2);
    }
#pragma unroll
    for (int o = 16; o; o >>= 1) {
        a0 += __shfl_xor_sync(0xffffffffu, a0, o);
        a1 += __shfl_xor_sync(0xffffffffu, a1, o);
        a2 += __shfl_xor_sync(0xffffffffu, a2, o);
    }
    if (lane == 0) g_aggx[wid] = make_float4(a0, a1, a2, 0.f);
}

// K7: hs1 = dinv * relu(dinv*agg0 @ W0 + b0). Thread per (node, feat-quad).
__global__ void k_node0(const float* __restrict__ W0, const float* __restrict__ b0, int n) {
    int t = blockIdx.x * blockDim.x + threadIdx.x;
    if (t >= n * 8) return;
    int i = t >> 3, j = t & 7;
    float4 a  = g_aggx[i];
    float dv  = g_dinv[i];
    a.x *= dv; a.y *= dv; a.z *= dv;
    float4 w0 = ((const float4*)(W0     ))[j];
    float4 w1 = ((const float4*)(W0 + 32))[j];
    float4 w2 = ((const float4*)(W0 + 64))[j];
    float4 bb = ((const float4*)(b0     ))[j];
    float4 h;
    h.x = fmaf(a.x, w0.x, fmaf(a.y, w1.x, fmaf(a.z, w2.x, bb.x)));
    h.y = fmaf(a.x, w0.y, fmaf(a.y, w1.y, fmaf(a.z, w2.y, bb.y)));
    h.z = fmaf(a.x, w0.z, fmaf(a.y, w1.z, fmaf(a.z, w2.z, bb.z)));
    h.w = fmaf(a.x, w0.w, fmaf(a.y, w1.w, fmaf(a.z, w2.w, bb.w)));
    h.x = fmaxf(h.x, 0.f) * dv; h.y = fmaxf(h.y, 0.f) * dv;
    h.z = fmaxf(h.z, 0.f) * dv; h.w = fmaxf(h.w, 0.f) * dv;
    g_h4[t] = h;
}

// K8: layer-1 pull: warp/node, 4 edge-groups x 8 feature-quads.
// Each edge's 128B source row is one fully-used gather; no atomics.
__global__ void k_pull1(int n) {
    int wid  = (blockIdx.x * blockDim.x + threadIdx.x) >> 5;
    int lane = threadIdx.x & 31;
    if (wid >= n) return;
    int g4 = lane >> 3, j = lane & 7;
    int s = g_off[wid], epos = g_off[wid + 1];
    float4 acc = (g4 == 0) ? g_h4[wid * 8 + j] : make_float4(0.f, 0.f, 0.f, 0.f);
    for (int e = s + g4; e < epos; e += 4) {
        int2 c = g_csr[e];
        float ww = __int_as_float(c.y);
        float4 v = g_h4[c.x * 8 + j];
        acc.x = fmaf(ww, v.x, acc.x); acc.y = fmaf(ww, v.y, acc.y);
        acc.z = fmaf(ww, v.z, acc.z); acc.w = fmaf(ww, v.w, acc.w);
    }
#pragma unroll
    for (int o = 8; o <= 16; o <<= 1) {
        acc.x += __shfl_xor_sync(0xffffffffu, acc.x, o);
        acc.y += __shfl_xor_sync(0xffffffffu, acc.y, o);
        acc.z += __shfl_xor_sync(0xffffffffu, acc.z, o);
        acc.w += __shfl_xor_sync(0xffffffffu, acc.w, o);
    }
    if (lane < 8) g_agg4[wid * 8 + j] = acc;  // 128B coalesced store
}

// K9: per-graph block: h2 = relu(dinv*agg1 @ W1 + b1), mean-pool, head.
__global__ void k_pool(const int* __restrict__ batch,
                       const float* __restrict__ W1, const float* __restrict__ b1,
                       const float* __restrict__ Wr, const float* __restrict__ br,
                       float* __restrict__ out, int n) {
    int g = blockIdx.x;
    __shared__ float sW1[32 * 32];
    __shared__ float sb1[32];
    __shared__ float sWr[32];
    __shared__ int   sse[2];
    __shared__ float stile[8][33];
    __shared__ float spool[8][32];
    int tid = threadIdx.x;  // 256 threads
    for (int k = tid; k < 1024; k += 256) sW1[k] = W1[k];
    if (tid < 32) { sb1[tid] = b1[tid]; sWr[tid] = Wr[tid]; }
    if (tid < 2) {
        int key = g + tid;
        int lo = 0, hi = n;
        while (lo < hi) { int mid = (lo + hi) >> 1; if (batch[mid] < key) lo = mid + 1; else hi = mid; }
        sse[tid] = lo;
    }
    __syncthreads();
    int start = sse[0], end = sse[1];
    int feat = tid & 31, slot = tid >> 5;
    const float* agg = (const float*)g_agg4;
    float acc = 0.f;
    for (int base = start; base < end; base += 8) {
        int nload = min(8, end - base);
        __syncthreads();
        if (slot < nload) {
            int node = base + slot;
            stile[slot][feat] = g_dinv[node] * agg[node * 32 + feat];
        }
        __syncthreads();
        if (slot < nload) {
            float v = sb1[feat];
#pragma unroll
            for (int jj = 0; jj < 32; jj++) v = fmaf(stile[slot][jj], sW1[jj * 32 + feat], v);
            acc += fmaxf(v, 0.f);
        }
    }
    spool[slot][feat] = acc;
    __syncthreads();
    if (tid < 32) {
        float s = 0.f;
#pragma unroll
        for (int k = 0; k < 8; k++) s += spool[k][tid];
        float cnt = (float)(end - start);
        float hg = s / fmaxf(cnt, 1.f);
        float p = hg * sWr[tid];
#pragma unroll
        for (int off = 16; off; off >>= 1) p += __shfl_down_sync(0xffffffffu, p, off);
        if (tid == 0) out[g] = p + br[0];
    }
}

extern "C" void kernel_launch(void* const* d_in, const int* in_sizes, int n_in,
                              void* d_out, int out_size) {
    const float* x     = (const float*)d_in[0];
    const int*   ei    = (const int*)d_in[1];
    const float* ew    = (const float*)d_in[2];
    const int*   batch = (const int*)d_in[3];
    const float* W0    = (const float*)d_in[4];
    const float* b0    = (const float*)d_in[5];
    const float* W1    = (const float*)d_in[6];
    const float* b1    = (const float*)d_in[7];
    const float* Wr    = (const float*)d_in[8];
    const float* br    = (const float*)d_in[9];
    float* out = (float*)d_out;

    int n = in_sizes[0] / 3;
    int E = in_sizes[2];
    int G = out_size;
    const int TB = 256;
    int warpGrid = (n * 32 + TB - 1) / TB;

    k_zero   <<<(n + 1 + TB - 1) / TB, TB>>>(n);
    k_hist   <<<(E + TB - 1) / TB, TB>>>(ei, E);
    k_scan   <<<1, 1024>>>(n);
    k_scatter<<<(E + TB - 1) / TB, TB>>>(ei, ew, E);
    k_degdinv<<<warpGrid, TB>>>(x, n);
    k_pull0  <<<warpGrid, TB>>>(n);
    k_node0  <<<(n * 8 + TB - 1) / TB, TB>>>(W0, b0, n);
    k_pull1  <<<warpGrid, TB>>>(n);
    k_pool   <<<G, 256>>>(batch, W1, b1, Wr, br, out, n);
}

// round 6
// speedup vs baseline: 1.9467x; 1.9467x over previous
#include <cuda_runtime.h>
#include <cuda_fp16.h>

#define MAXN 100000

// ---- device scratch (no allocations allowed) ----
__device__ float g_deg [MAXN];
__device__ float g_dinv[MAXN];
__device__ __align__(128) float4 g_xp  [MAXN];      // xs = dinv*x, padded (w=0)
__device__ __align__(128) float4 g_aggx[MAXN];      // layer-0 agg of xs (seeded w/ self)
__device__ __align__(128) uint2  g_h2  [MAXN * 8];  // hs1 in fp16: 4 halves per uint2
__device__ __align__(128) float4 g_agg4[MAXN * 8];  // layer-1 agg (fp32)  [N x 32]

__device__ __forceinline__ void red_add_v4(float4* addr, float4 v) {
    atomicAdd(addr, v);   // native vector red (cc >= 9.0)
}

// K1: deg starts at 1.0 (self-loop weight)
__global__ void k_init(int n) {
    int i = blockIdx.x * blockDim.x + threadIdx.x;
    if (i < n) g_deg[i] = 1.0f;
}

// K2: deg[col] += w over all edges
__global__ void k_deg(const int* __restrict__ idx, const float* __restrict__ w, int E) {
    int e = blockIdx.x * blockDim.x + threadIdx.x;
    if (e >= E) return;
    atomicAdd(&g_deg[idx[E + e]], w[e]);
}

// K3: dinv = rsqrt(deg); xs = dinv*x; seed layer-0 agg with self term xs
__global__ void k_dinv(const float* __restrict__ x, int n) {
    int i = blockIdx.x * blockDim.x + threadIdx.x;
    if (i >= n) return;
    float d  = g_deg[i];
    float dv = d > 0.f ? rsqrtf(d) : 0.f;
    g_dinv[i] = dv;
    float4 xs = make_float4(x[3*i] * dv, x[3*i+1] * dv, x[3*i+2] * dv, 0.f);
    g_xp[i]   = xs;
    g_aggx[i] = xs;
}

// K4: layer-0 edge pass (factorized norm: no per-edge dinv)
__global__ void k_edge0(const int* __restrict__ idx, const float* __restrict__ w, int E) {
    int e = blockIdx.x * blockDim.x + threadIdx.x;
    if (e >= E) return;
    int row = idx[e];
    int col = idx[E + e];
    float ww = w[e];
    float4 v = g_xp[row];
    red_add_v4(&g_aggx[col], make_float4(v.x * ww, v.y * ww, v.z * ww, 0.f));
}

// K5: hs1 = dinv*relu(dinv*agg0 @ W0 + b0); store fp16 (gather payload),
// seed layer-1 agg with exact fp32 self term. Thread per (node, feat-quad).
__global__ void k_node0(const float* __restrict__ W0, const float* __restrict__ b0, int n) {
    int t = blockIdx.x * blockDim.x + threadIdx.x;
    if (t >= n * 8) return;
    int i = t >> 3, j = t & 7;
    float4 a  = g_aggx[i];
    float dv  = g_dinv[i];
    a.x *= dv; a.y *= dv; a.z *= dv;
    float4 w0 = ((const float4*)(W0     ))[j];
    float4 w1 = ((const float4*)(W0 + 32))[j];
    float4 w2 = ((const float4*)(W0 + 64))[j];
    float4 bb = ((const float4*)(b0     ))[j];
    float4 h;
    h.x = fmaf(a.x, w0.x, fmaf(a.y, w1.x, fmaf(a.z, w2.x, bb.x)));
    h.y = fmaf(a.x, w0.y, fmaf(a.y, w1.y, fmaf(a.z, w2.y, bb.y)));
    h.z = fmaf(a.x, w0.z, fmaf(a.y, w1.z, fmaf(a.z, w2.z, bb.z)));
    h.w = fmaf(a.x, w0.w, fmaf(a.y, w1.w, fmaf(a.z, w2.w, bb.w)));
    h.x = fmaxf(h.x, 0.f) * dv; h.y = fmaxf(h.y, 0.f) * dv;
    h.z = fmaxf(h.z, 0.f) * dv; h.w = fmaxf(h.w, 0.f) * dv;
    half2 lo = __floats2half2_rn(h.x, h.y);
    half2 hi = __floats2half2_rn(h.z, h.w);
    uint2 p;
    p.x = *(unsigned int*)&lo;
    p.y = *(unsigned int*)&hi;
    g_h2[t]   = p;
    g_agg4[t] = h;   // exact self-loop seed
}

// K6: layer-1 edge pass — 8 lanes per edge, lane j owns feature-quad j.
// fp16 gather (8B/lane, 64B/edge) + fp32 red.v4 scatter.
__global__ void k_edge1(const int* __restrict__ idx, const float* __restrict__ w, int E) {
    int t = blockIdx.x * blockDim.x + threadIdx.x;
    int e = t >> 3;
    if (e >= E) return;
    int j   = t & 7;
    int row = idx[e];
    int col = idx[E + e];
    float ww = w[e];
    uint2 p = g_h2[row * 8 + j];
    float2 f0 = __half22float2(*(half2*)&p.x);
    float2 f1 = __half22float2(*(half2*)&p.y);
    red_add_v4(&g_agg4[col * 8 + j],
               make_float4(f0.x * ww, f0.y * ww, f1.x * ww, f1.y * ww));
}

// K7: per-graph block: h2 = relu(dinv*agg1 @ W1 + b1), mean-pool over
// sorted-batch range (binary search), head dot with Wr.
__global__ void k_pool(const int* __restrict__ batch,
                       const float* __restrict__ W1, const float* __restrict__ b1,
                       const float* __restrict__ Wr, const float* __restrict__ br,
                       float* __restrict__ out, int n) {
    int g = blockIdx.x;
    __shared__ float sW1[32 * 32];
    __shared__ float sb1[32];
    __shared__ float sWr[32];
    __shared__ int   sse[2];
    __shared__ float stile[8][33];
    __shared__ float spool[8][32];
    int tid = threadIdx.x;  // 256 threads
    for (int k = tid; k < 1024; k += 256) sW1[k] = W1[k];
    if (tid < 32) { sb1[tid] = b1[tid]; sWr[tid] = Wr[tid]; }
    if (tid < 2) {
        int key = g + tid;
        int lo = 0, hi = n;
        while (lo < hi) { int mid = (lo + hi) >> 1; if (batch[mid] < key) lo = mid + 1; else hi = mid; }
        sse[tid] = lo;
    }
    __syncthreads();
    int start = sse[0], end = sse[1];
    int feat = tid & 31, slot = tid >> 5;
    const float* agg = (const float*)g_agg4;
    float acc = 0.f;
    for (int base = start; base < end; base += 8) {
        int nload = min(8, end - base);
        __syncthreads();
        if (slot < nload) {
            int node = base + slot;
            stile[slot][feat] = g_dinv[node] * agg[node * 32 + feat];
        }
        __syncthreads();
        if (slot < nload) {
            float v = sb1[feat];
#pragma unroll
            for (int jj = 0; jj < 32; jj++) v = fmaf(stile[slot][jj], sW1[jj * 32 + feat], v);
            acc += fmaxf(v, 0.f);
        }
    }
    spool[slot][feat] = acc;
    __syncthreads();
    if (tid < 32) {
        float s = 0.f;
#pragma unroll
        for (int k = 0; k < 8; k++) s += spool[k][tid];
        float cnt = (float)(end - start);
        float hg = s / fmaxf(cnt, 1.f);
        float p = hg * sWr[tid];
#pragma unroll
        for (int off = 16; off; off >>= 1) p += __shfl_down_sync(0xffffffffu, p, off);
        if (tid == 0) out[g] = p + br[0];
    }
}

extern "C" void kernel_launch(void* const* d_in, const int* in_sizes, int n_in,
                              void* d_out, int out_size) {
    const float* x     = (const float*)d_in[0];
    const int*   ei    = (const int*)d_in[1];
    const float* ew    = (const float*)d_in[2];
    const int*   batch = (const int*)d_in[3];
    const float* W0    = (const float*)d_in[4];
    const float* b0    = (const float*)d_in[5];
    const float* W1    = (const float*)d_in[6];
    const float* b1    = (const float*)d_in[7];
    const float* Wr    = (const float*)d_in[8];
    const float* br    = (const float*)d_in[9];
    float* out = (float*)d_out;

    int n = in_sizes[0] / 3;
    int E = in_sizes[2];
    int G = out_size;
    const int TB = 256;

    k_init <<<(n + TB - 1) / TB, TB>>>(n);
    k_deg  <<<(E + TB - 1) / TB, TB>>>(ei, ew, E);
    k_dinv <<<(n + TB - 1) / TB, TB>>>(x, n);
    k_edge0<<<(E + TB - 1) / TB, TB>>>(ei, ew, E);
    k_node0<<<(n * 8 + TB - 1) / TB, TB>>>(W0, b0, n);
    long long t1 = (long long)E * 8;
    k_edge1<<<(int)((t1 + TB - 1) / TB), TB>>>(ei, ew, E);
    k_pool <<<G, 256>>>(batch, W1, b1, Wr, br, out, n);
}

// round 8
// speedup vs baseline: 2.2579x; 1.1599x over previous
#include <cuda_runtime.h>
#include <cuda_fp16.h>
#include <cstdint>

#define MAXN 100000

// ---- device scratch (no allocations allowed) ----
__device__ float g_deg [MAXN];
__device__ float g_dinv[MAXN];
__device__ __align__(128) float4 g_xp  [MAXN];      // xs = dinv*x, padded (w=0)
__device__ __align__(128) float4 g_aggx[MAXN];      // layer-0 agg of xs (seeded w/ self)
__device__ __align__(128) uint2  g_h2  [MAXN * 8];  // hs1 fp16 [N x 32], 4 halves/uint2
__device__ __align__(128) uint2  g_aggh[MAXN * 8];  // layer-1 agg fp16 [N x 32]

__device__ __forceinline__ void red_add_v4f(float4* addr, float4 v) {
    atomicAdd(addr, v);   // native fp32 vector red (cc >= 9.0)
}

// fp16x2 vector red: one 16B op carries 8 halves
__device__ __forceinline__ void red_add_v4h(void* addr, unsigned int a, unsigned int b,
                                            unsigned int c, unsigned int d) {
    asm volatile("red.global.add.noftz.v4.f16x2 [%0], {%1,%2,%3,%4};"
                 :: "l"(__cvta_generic_to_global(addr)),
                    "r"(a), "r"(b), "r"(c), "r"(d) : "memory");
}

// K1: deg starts at 1.0 (self-loop weight)
__global__ void k_init(int n) {
    int i = blockIdx.x * blockDim.x + threadIdx.x;
    if (i < n) g_deg[i] = 1.0f;
}

// K2: deg[col] += w over all edges
__global__ void k_deg(const int* __restrict__ idx, const float* __restrict__ w, int E) {
    int e = blockIdx.x * blockDim.x + threadIdx.x;
    if (e >= E) return;
    atomicAdd(&g_deg[idx[E + e]], w[e]);
}

// K3: dinv = rsqrt(deg); xs = dinv*x; seed layer-0 agg with self term xs
__global__ void k_dinv(const float* __restrict__ x, int n) {
    int i = blockIdx.x * blockDim.x + threadIdx.x;
    if (i >= n) return;
    float d  = g_deg[i];
    float dv = d > 0.f ? rsqrtf(d) : 0.f;
    g_dinv[i] = dv;
    float4 xs = make_float4(x[3*i] * dv, x[3*i+1] * dv, x[3*i+2] * dv, 0.f);
    g_xp[i]   = xs;
    g_aggx[i] = xs;
}

// K4: layer-0 edge pass (factorized norm: no per-edge dinv), fp32
__global__ void k_edge0(const int* __restrict__ idx, const float* __restrict__ w, int E) {
    int e = blockIdx.x * blockDim.x + threadIdx.x;
    if (e >= E) return;
    int row = idx[e];
    int col = idx[E + e];
    float ww = w[e];
    float4 v = g_xp[row];
    red_add_v4f(&g_aggx[col], make_float4(v.x * ww, v.y * ww, v.z * ww, 0.f));
}

// K5: hs1 = dinv*relu(dinv*agg0 @ W0 + b0); store fp16; seed fp16 layer-1 agg
// with the self term. Thread per (node, feat-quad).
__global__ void k_node0(const float* __restrict__ W0, const float* __restrict__ b0, int n) {
    int t = blockIdx.x * blockDim.x + threadIdx.x;
    if (t >= n * 8) return;
    int i = t >> 3, j = t & 7;
    float4 a  = g_aggx[i];
    float dv  = g_dinv[i];
    a.x *= dv; a.y *= dv; a.z *= dv;
    float4 w0 = ((const float4*)(W0     ))[j];
    float4 w1 = ((const float4*)(W0 + 32))[j];
    float4 w2 = ((const float4*)(W0 + 64))[j];
    float4 bb = ((const float4*)(b0     ))[j];
    float4 h;
    h.x = fmaf(a.x, w0.x, fmaf(a.y, w1.x, fmaf(a.z, w2.x, bb.x)));
    h.y = fmaf(a.x, w0.y, fmaf(a.y, w1.y, fmaf(a.z, w2.y, bb.y)));
    h.z = fmaf(a.x, w0.z, fmaf(a.y, w1.z, fmaf(a.z, w2.z, bb.z)));
    h.w = fmaf(a.x, w0.w, fmaf(a.y, w1.w, fmaf(a.z, w2.w, bb.w)));
    h.x = fmaxf(h.x, 0.f) * dv; h.y = fmaxf(h.y, 0.f) * dv;
    h.z = fmaxf(h.z, 0.f) * dv; h.w = fmaxf(h.w, 0.f) * dv;
    half2 lo = __floats2half2_rn(h.x, h.y);
    half2 hi = __floats2half2_rn(h.z, h.w);
    uint2 p;
    p.x = *(unsigned int*)&lo;
    p.y = *(unsigned int*)&hi;
    g_h2[t]   = p;
    g_aggh[t] = p;   // self-loop seed (fp16)
}

// K6: layer-1 edge pass — 4 lanes per edge, lane j owns a 16B (8-half) chunk.
// One LDG.128 gather + one red.v4.f16x2 per lane: 2 ops/lane, 8 ops/edge total.
__global__ void k_edge1(const int* __restrict__ idx, const float* __restrict__ w, int E) {
    int t = blockIdx.x * blockDim.x + threadIdx.x;
    int e = t >> 2;
    if (e >= E) return;
    int j   = t & 3;
    int row = idx[e];
    int col = idx[E + e];
    half2 ws = __float2half2_rn(w[e]);
    uint4 p = ((const uint4*)g_h2)[row * 4 + j];
    half2 h0 = __hmul2(*(half2*)&p.x, ws);
    half2 h1 = __hmul2(*(half2*)&p.y, ws);
    half2 h2 = __hmul2(*(half2*)&p.z, ws);
    half2 h3 = __hmul2(*(half2*)&p.w, ws);
    red_add_v4h(&((uint4*)g_aggh)[col * 4 + j],
                *(unsigned int*)&h0, *(unsigned int*)&h1,
                *(unsigned int*)&h2, *(unsigned int*)&h3);
}

// K7: per-graph block: h2 = relu(dinv*agg1 @ W1 + b1), mean-pool over
// sorted-batch range (binary search), head dot with Wr.
__global__ void k_pool(const int* __restrict__ batch,
                       const float* __restrict__ W1, const float* __restrict__ b1,
                       const float* __restrict__ Wr, const float* __restrict__ br,
                       float* __restrict__ out, int n) {
    int g = blockIdx.x;
    __shared__ float sW1[32 * 32];
    __shared__ float sb1[32];
    __shared__ float sWr[32];
    __shared__ int   sse[2];
    __shared__ float stile[8][33];
    __shared__ float spool[8][32];
    int tid = threadIdx.x;  // 256 threads
    for (int k = tid; k < 1024; k += 256) sW1[k] = W1[k];
    if (tid < 32) { sb1[tid] = b1[tid]; sWr[tid] = Wr[tid]; }
    if (tid < 2) {
        int key = g + tid;
        int lo = 0, hi = n;
        while (lo < hi) { int mid = (lo + hi) >> 1; if (batch[mid] < key) lo = mid + 1; else hi = mid; }
        sse[tid] = lo;
    }
    __syncthreads();
    int start = sse[0], end = sse[1];
    int feat = tid & 31, slot = tid >> 5;
    const __half* agg = (const __half*)g_aggh;
    float acc = 0.f;
    for (int base = start; base < end; base += 8) {
        int nload = min(8, end - base);
        __syncthreads();
        if (slot < nload) {
            int node = base + slot;
            stile[slot][feat] = g_dinv[node] * __half2float(agg[node * 32 + feat]);
        }
        __syncthreads();
        if (slot < nload) {
            float v = sb1[feat];
#pragma unroll
            for (int jj = 0; jj < 32; jj++) v = fmaf(stile[slot][jj], sW1[jj * 32 + feat], v);
            acc += fmaxf(v, 0.f);
        }
    }
    spool[slot][feat] = acc;
    __syncthreads();
    if (tid < 32) {
        float s = 0.f;
#pragma unroll
        for (int k = 0; k < 8; k++) s += spool[k][tid];
        float cnt = (float)(end - start);
        float hg = s / fmaxf(cnt, 1.f);
        float p = hg * sWr[tid];
#pragma unroll
        for (int off = 16; off; off >>= 1) p += __shfl_down_sync(0xffffffffu, p, off);
        if (tid == 0) out[g] = p + br[0];
    }
}

extern "C" void kernel_launch(void* const* d_in, const int* in_sizes, int n_in,
                              void* d_out, int out_size) {
    const float* x     = (const float*)d_in[0];
    const int*   ei    = (const int*)d_in[1];
    const float* ew    = (const float*)d_in[2];
    const int*   batch = (const int*)d_in[3];
    const float* W0    = (const float*)d_in[4];
    const float* b0    = (const float*)d_in[5];
    const float* W1    = (const float*)d_in[6];
    const float* b1    = (const float*)d_in[7];
    const float* Wr    = (const float*)d_in[8];
    const float* br    = (const float*)d_in[9];
    float* out = (float*)d_out;

    int n = in_sizes[0] / 3;
    int E = in_sizes[2];
    int G = out_size;
    const int TB = 256;

    k_init <<<(n + TB - 1) / TB, TB>>>(n);
    k_deg  <<<(E + TB - 1) / TB, TB>>>(ei, ew, E);
    k_dinv <<<(n + TB - 1) / TB, TB>>>(x, n);
    k_edge0<<<(E + TB - 1) / TB, TB>>>(ei, ew, E);
    k_node0<<<(n * 8 + TB - 1) / TB, TB>>>(W0, b0, n);
    long long t1 = (long long)E * 4;
    k_edge1<<<(int)((t1 + TB - 1) / TB), TB>>>(ei, ew, E);
    k_pool <<<G, 256>>>(batch, W1, b1, Wr, br, out, n);
}